// round 1
// baseline (speedup 1.0000x reference)
#include <cuda_runtime.h>

// Problem constants (fixed by the dataset)
#define BSZ   16384
#define KNUM  1000
#define DIMN  768

#define WARPS_PER_BLOCK 8
#define THREADS (WARPS_PER_BLOCK * 32)

// DIMN/4 float4 per row = 192; per lane = 192/32 = 6
#define V4_PER_LANE 6
// mask row: KNUM/4 = 250 float4
#define MASK_V4 (KNUM / 4)

__global__ __launch_bounds__(THREADS)
void css_kernel(const float* __restrict__ mask,   // [BS, K]
                const float* __restrict__ z,      // [BS, DIM]
                const float* __restrict__ S,      // [K, 2*DIM]
                const float* __restrict__ A,      // [K, 2]
                const float* __restrict__ LG,     // [K, 2]
                float* __restrict__ out)          // [BS, DIM]
{
    const int warp = (blockIdx.x * THREADS + threadIdx.x) >> 5;
    const int lane = threadIdx.x & 31;
    if (warp >= BSZ) return;

    // ---- 1. Find the one-hot index for this sample (coalesced float4 scan)
    const float4* __restrict__ mrow =
        reinterpret_cast<const float4*>(mask + (size_t)warp * KNUM);
    int idx = 0;
    #pragma unroll
    for (int it = 0; it < 8; it++) {
        int i = lane + 32 * it;
        if (i < MASK_V4) {
            float4 v = __ldg(&mrow[i]);
            if (v.x != 0.0f) idx = 4 * i + 0;
            if (v.y != 0.0f) idx = 4 * i + 1;
            if (v.z != 0.0f) idx = 4 * i + 2;
            if (v.w != 0.0f) idx = 4 * i + 3;
        }
    }
    #pragma unroll
    for (int o = 16; o > 0; o >>= 1)
        idx = max(idx, __shfl_xor_sync(0xffffffffu, idx, o));

    // ---- 2. Per-dipole scalars (tiny gathers; L2/L1 resident)
    const float a0 = __ldg(&A[2 * idx + 0]);
    const float a1 = __ldg(&A[2 * idx + 1]);
    const float g0 = __expf(__ldg(&LG[2 * idx + 0]));
    const float g1 = __expf(__ldg(&LG[2 * idx + 1]));

    // ---- 3. Load z and both support poles; form D = z - s, accumulate ||D||^2
    const float4* __restrict__ zrow =
        reinterpret_cast<const float4*>(z + (size_t)warp * DIMN);
    const float4* __restrict__ s0r =
        reinterpret_cast<const float4*>(S + (size_t)idx * (2 * DIMN));
    const float4* __restrict__ s1r = s0r + (DIMN / 4);

    float4 zr[V4_PER_LANE], d0[V4_PER_LANE], d1[V4_PER_LANE];
    float sq0 = 0.0f, sq1 = 0.0f;
    #pragma unroll
    for (int i = 0; i < V4_PER_LANE; i++) {
        const int p = lane + 32 * i;
        float4 zv = __ldg(&zrow[p]);
        float4 s0 = __ldg(&s0r[p]);
        float4 s1 = __ldg(&s1r[p]);
        zr[i] = zv;
        d0[i].x = zv.x - s0.x;  d0[i].y = zv.y - s0.y;
        d0[i].z = zv.z - s0.z;  d0[i].w = zv.w - s0.w;
        d1[i].x = zv.x - s1.x;  d1[i].y = zv.y - s1.y;
        d1[i].z = zv.z - s1.z;  d1[i].w = zv.w - s1.w;
        sq0 = fmaf(d0[i].x, d0[i].x, sq0);
        sq0 = fmaf(d0[i].y, d0[i].y, sq0);
        sq0 = fmaf(d0[i].z, d0[i].z, sq0);
        sq0 = fmaf(d0[i].w, d0[i].w, sq0);
        sq1 = fmaf(d1[i].x, d1[i].x, sq1);
        sq1 = fmaf(d1[i].y, d1[i].y, sq1);
        sq1 = fmaf(d1[i].z, d1[i].z, sq1);
        sq1 = fmaf(d1[i].w, d1[i].w, sq1);
    }
    #pragma unroll
    for (int o = 16; o > 0; o >>= 1) {
        sq0 += __shfl_xor_sync(0xffffffffu, sq0, o);
        sq1 += __shfl_xor_sync(0xffffffffu, sq1, o);
    }

    // ---- 4. RBF weights; grad = w0*D0 + w1*D1 ; accumulate z . grad
    const float w0 = -2.0f * a0 * g0 * __expf(-g0 * sq0);
    const float w1 = -2.0f * a1 * g1 * __expf(-g1 * sq1);

    float zg = 0.0f;
    #pragma unroll
    for (int i = 0; i < V4_PER_LANE; i++) {
        // grad overwrites d0
        d0[i].x = fmaf(w1, d1[i].x, w0 * d0[i].x);
        d0[i].y = fmaf(w1, d1[i].y, w0 * d0[i].y);
        d0[i].z = fmaf(w1, d1[i].z, w0 * d0[i].z);
        d0[i].w = fmaf(w1, d1[i].w, w0 * d0[i].w);
        zg = fmaf(zr[i].x, d0[i].x, zg);
        zg = fmaf(zr[i].y, d0[i].y, zg);
        zg = fmaf(zr[i].z, d0[i].z, zg);
        zg = fmaf(zr[i].w, d0[i].w, zg);
    }
    #pragma unroll
    for (int o = 16; o > 0; o >>= 1)
        zg += __shfl_xor_sync(0xffffffffu, zg, o);

    // ---- 5. Tangent projection, norm, normalize, store
    float nrm = 0.0f;
    #pragma unroll
    for (int i = 0; i < V4_PER_LANE; i++) {
        // proj overwrites d0 (grad)
        d0[i].x = fmaf(-zg, zr[i].x, d0[i].x);
        d0[i].y = fmaf(-zg, zr[i].y, d0[i].y);
        d0[i].z = fmaf(-zg, zr[i].z, d0[i].z);
        d0[i].w = fmaf(-zg, zr[i].w, d0[i].w);
        nrm = fmaf(d0[i].x, d0[i].x, nrm);
        nrm = fmaf(d0[i].y, d0[i].y, nrm);
        nrm = fmaf(d0[i].z, d0[i].z, nrm);
        nrm = fmaf(d0[i].w, d0[i].w, nrm);
    }
    #pragma unroll
    for (int o = 16; o > 0; o >>= 1)
        nrm += __shfl_xor_sync(0xffffffffu, nrm, o);

    const float inv = rsqrtf(nrm);

    float4* __restrict__ orow =
        reinterpret_cast<float4*>(out + (size_t)warp * DIMN);
    #pragma unroll
    for (int i = 0; i < V4_PER_LANE; i++) {
        float4 o4;
        o4.x = d0[i].x * inv;
        o4.y = d0[i].y * inv;
        o4.z = d0[i].z * inv;
        o4.w = d0[i].w * inv;
        orow[lane + 32 * i] = o4;
    }
}

extern "C" void kernel_launch(void* const* d_in, const int* in_sizes, int n_in,
                              void* d_out, int out_size)
{
    const float* mask = (const float*)d_in[0];   // [BS, K]
    const float* z    = (const float*)d_in[1];   // [BS, DIM]
    const float* S    = (const float*)d_in[2];   // [K, 2*DIM]
    const float* A    = (const float*)d_in[3];   // [K, 2]
    const float* LG   = (const float*)d_in[4];   // [K, 2]
    float* out        = (float*)d_out;           // [BS, DIM]

    const int blocks = BSZ / WARPS_PER_BLOCK;    // 2048
    css_kernel<<<blocks, THREADS>>>(mask, z, S, A, LG, out);
}